// round 9
// baseline (speedup 1.0000x reference)
#include <cuda_runtime.h>
#include <cuda_fp16.h>
#include <cstdint>

#define DINLINE __device__ __forceinline__

// ---------------- problem constants ----------------
#define ROWS_TOTAL 32768      // B*N = 8*4096
#define CDIM 768
#define NB 8
#define INV_NTOT (1.0f/25165824.0f)   // 1 / (B*H*W*C)
#define LAMBDA 0.01f

// ---------------- device scratch ----------------
__device__ __half g_cas[CDIM * CDIM];                  // symmetric
__device__ __half g_Xh[(size_t)ROWS_TOTAL * CDIM];
__device__ __half g_Y[(size_t)ROWS_TOTAL * CDIM];
__device__ __half g_D[(size_t)ROWS_TOTAL * CDIM];
__device__ __half g_W1T[NB * 192 * 96];
__device__ __half g_W2T[NB * 192 * 192];

// ---------------- asm helpers ----------------
DINLINE void ldsm4(uint32_t& r0, uint32_t& r1, uint32_t& r2, uint32_t& r3, const void* p) {
    uint32_t a = (uint32_t)__cvta_generic_to_shared(p);
    asm volatile("ldmatrix.sync.aligned.m8n8.x4.shared.b16 {%0,%1,%2,%3}, [%4];"
                 : "=r"(r0), "=r"(r1), "=r"(r2), "=r"(r3) : "r"(a));
}
// fp16 accumulate (2x rate): C/D = 2 x f16x2 regs
DINLINE void mma_h(uint32_t& c0, uint32_t& c1, const uint32_t* a, const uint32_t* b) {
    asm volatile("mma.sync.aligned.m16n8k16.row.col.f16.f16.f16.f16 "
                 "{%0,%1}, {%2,%3,%4,%5}, {%6,%7}, {%0,%1};"
                 : "+r"(c0), "+r"(c1)
                 : "r"(a[0]), "r"(a[1]), "r"(a[2]), "r"(a[3]),
                   "r"(b[0]), "r"(b[1]));
}
DINLINE void cpa16(void* smem, const void* g) {
    uint32_t a = (uint32_t)__cvta_generic_to_shared(smem);
    asm volatile("cp.async.cg.shared.global [%0], [%1], 16;" :: "r"(a), "l"(g));
}
DINLINE void cp_commit() { asm volatile("cp.async.commit_group;"); }
template<int N> DINLINE void cp_wait() { asm volatile("cp.async.wait_group %0;" :: "n"(N)); }

// ---------------- fused prep kernel (one launch) ----------------
constexpr int PX_BLOCKS  = 24576;   // 6,291,456 float4 / 256
constexpr int PCAS_BLOCKS = 2304;   // 589,824 / 256
constexpr int PW1_BLOCKS = 576;     // 147,456 / 256
constexpr int PW2_BLOCKS = 1152;    // 294,912 / 256
constexpr int PREP_BLOCKS = PX_BLOCKS + PCAS_BLOCKS + PW1_BLOCKS + PW2_BLOCKS;

__global__ void prep_all(const float* __restrict__ x,
                         const float* __restrict__ w1,
                         const float* __restrict__ w2) {
    int bid = blockIdx.x, tid = threadIdx.x;
    if (bid < PX_BLOCKS) {
        size_t i = ((size_t)bid * 256 + tid) * 4;
        float4 v = *(const float4*)&x[i];
        __half2 h0, h1;
        h0.x = __float2half(v.x); h0.y = __float2half(v.y);
        h1.x = __float2half(v.z); h1.y = __float2half(v.w);
        *(__half2*)&g_Xh[i]     = h0;
        *(__half2*)&g_Xh[i + 2] = h1;
    } else if (bid < PX_BLOCKS + PCAS_BLOCKS) {
        int idx = (bid - PX_BLOCKS) * 256 + tid;
        int i = idx / CDIM, j = idx % CDIM;
        int p = (int)(((long long)i * (long long)j) % CDIM);
        float ang = (float)p * (6.28318530717958647692f / (float)CDIM);
        g_cas[idx] = __float2half(cosf(ang) + sinf(ang));
    } else if (bid < PX_BLOCKS + PCAS_BLOCKS + PW1_BLOCKS) {
        int idx = (bid - PX_BLOCKS - PCAS_BLOCKS) * 256 + tid;
        int i = idx % 96;
        int n = (idx / 96) % 192;
        int k = idx / (96 * 192);
        float v = (n < 96) ? w1[((0 * NB + k) * 96 + i) * 96 + n]
                           : w1[((1 * NB + k) * 96 + i) * 96 + (n - 96)];
        g_W1T[idx] = __float2half(v);
    } else {
        int idx = (bid - PX_BLOCKS - PCAS_BLOCKS - PW1_BLOCKS) * 256 + tid;
        int j = idx % 192;
        int c = (idx / 192) % 192;
        int k = idx / (192 * 192);
        float v;
        if (c < 96) {
            v = (j < 96) ?  w2[((0 * NB + k) * 96 + j) * 96 + c]
                         : -w2[((1 * NB + k) * 96 + (j - 96)) * 96 + c];
        } else {
            int cc = c - 96;
            v = (j < 96) ?  w2[((1 * NB + k) * 96 + j) * 96 + cc]
                         :  w2[((0 * NB + k) * 96 + (j - 96)) * 96 + cc];
        }
        g_W2T[idx] = __float2half(v);
    }
}

// ---------------- big GEMM: [32768,768] @ cas[768,768] ----------------
// BM=256, BN=128, warp tile 64x64, fp16 accum, 3-stage cp.async, 2 CTAs/SM.
constexpr int G_BK = 32;
constexpr int G_AST = G_BK + 8;                              // 40 halves/row
constexpr int G_A_ELEMS = 256 * G_AST;
constexpr int G_B_ELEMS = 128 * G_AST;
constexpr int G_STAGE_ELEMS = G_A_ELEMS + G_B_ELEMS;         // 15360
constexpr int G_SMEM = 3 * G_STAGE_ELEMS * 2;                // 92160 B
constexpr int G_NIT = CDIM / G_BK;                           // 24

DINLINE void g_fill(__half* sh, int s, int k0,
                    const __half* __restrict__ Ag,
                    int m0, int n0, int tid) {
    __half* As = sh + s * G_STAGE_ELEMS;
    __half* Bs = As + G_A_ELEMS;
#pragma unroll
    for (int e = tid; e < 1024; e += 256) {      // A: 256 rows x 4 chunks
        int r = e >> 2, c = (e & 3) << 3;
        cpa16(&As[r * G_AST + c], &Ag[(size_t)(m0 + r) * CDIM + k0 + c]);
    }
#pragma unroll
    for (int e = tid; e < 512; e += 256) {       // B: 128 rows x 4 chunks
        int r = e >> 2, c = (e & 3) << 3;
        cpa16(&Bs[r * G_AST + c], &g_cas[(size_t)(n0 + r) * CDIM + k0 + c]);
    }
}

template<int MODE>
__global__ void __launch_bounds__(256, 2) gemm768(const float* __restrict__ xbias,
                                                  float* __restrict__ outp) {
    extern __shared__ __half sh[];
    const int n0 = blockIdx.x * 128, m0 = blockIdx.y * 256;
    const int tid = threadIdx.x, lane = tid & 31, w = tid >> 5;
    const int wm = (w & 3) * 64, wn = (w >> 2) * 64;
    const __half* Ag = (MODE == 0) ? g_Xh : g_D;

    uint32_t acc[4][8][2];        // 64x64 fp16 tile
#pragma unroll
    for (int a = 0; a < 4; a++)
#pragma unroll
        for (int b = 0; b < 8; b++) { acc[a][b][0] = 0u; acc[a][b][1] = 0u; }

    g_fill(sh, 0, 0, Ag, m0, n0, tid); cp_commit();
    g_fill(sh, 1, G_BK, Ag, m0, n0, tid); cp_commit();

#pragma unroll 1
    for (int it = 0; it < G_NIT; it++) {
        cp_wait<1>();
        __syncthreads();
        if (it + 2 < G_NIT)
            g_fill(sh, (it + 2) % 3, (it + 2) * G_BK, Ag, m0, n0, tid);
        cp_commit();

        const __half* As = sh + (it % 3) * G_STAGE_ELEMS;
        const __half* Bs = As + G_A_ELEMS;
#pragma unroll
        for (int kk = 0; kk < G_BK; kk += 16) {
            uint32_t af[4][4];
#pragma unroll
            for (int mt = 0; mt < 4; mt++)
                ldsm4(af[mt][0], af[mt][1], af[mt][2], af[mt][3],
                      &As[(wm + mt * 16 + (lane & 15)) * G_AST + kk + ((lane >> 4) << 3)]);
#pragma unroll
            for (int q = 0; q < 4; q++) {
                uint32_t bfr[2][2];
                int nrow = wn + q * 16 + (lane & 7) + ((lane >> 4) & 1) * 8;
                int koff = kk + (lane & 8);
                ldsm4(bfr[0][0], bfr[0][1], bfr[1][0], bfr[1][1], &Bs[nrow * G_AST + koff]);
#pragma unroll
                for (int mt = 0; mt < 4; mt++) {
                    mma_h(acc[mt][2 * q + 0][0], acc[mt][2 * q + 0][1], af[mt], bfr[0]);
                    mma_h(acc[mt][2 * q + 1][0], acc[mt][2 * q + 1][1], af[mt], bfr[1]);
                }
            }
        }
    }

    const int g = lane >> 2, c2 = (lane & 3) << 1;
#pragma unroll
    for (int mt = 0; mt < 4; mt++) {
#pragma unroll
        for (int nt = 0; nt < 8; nt++) {
            int col = n0 + wn + nt * 8 + c2;
            int row = m0 + wm + mt * 16 + g;
            if (MODE == 0) {
                *(uint32_t*)&g_Y[(size_t)row * CDIM + col]       = acc[mt][nt][0];
                *(uint32_t*)&g_Y[(size_t)(row + 8) * CDIM + col] = acc[mt][nt][1];
            } else {
                float2 v0 = __half22float2(*(__half2*)&acc[mt][nt][0]);
                float2 v1 = __half22float2(*(__half2*)&acc[mt][nt][1]);
                float2 xv0 = *(const float2*)&xbias[(size_t)row * CDIM + col];
                float2 xv1 = *(const float2*)&xbias[(size_t)(row + 8) * CDIM + col];
                float2 o0, o1;
                o0.x = v0.x * INV_NTOT + xv0.x;
                o0.y = v0.y * INV_NTOT + xv0.y;
                o1.x = v1.x * INV_NTOT + xv1.x;
                o1.y = v1.y * INV_NTOT + xv1.y;
                *(float2*)&outp[(size_t)row * CDIM + col] = o0;
                *(float2*)&outp[(size_t)(row + 8) * CDIM + col] = o1;
            }
        }
    }
}

// ---------------- fused block-diagonal MLP: 512 threads, 256-row tiles ----------------
constexpr int MLP_SMEM = 196352;

__global__ void __launch_bounds__(512) mlp_kernel(const float* __restrict__ b1,
                                                  const float* __restrict__ b2) {
    extern __shared__ char smem[];
    __half* Ys  = (__half*)(smem);               // 256 x 104 (phase A / exchange)
    __half* W1s = (__half*)(smem + 53248);       // 192 x 104
    __half* W2s = (__half*)(smem);               // 192 x 200 (phase B, overlaps R0)
    __half* O1s = (__half*)(smem + 93184);       // 256 x 200
    __half2* bias1h = (__half2*)(smem + 195584); // 96 pairs
    __half2* bias2h = bias1h + 96;

    const int m0 = blockIdx.x * 256;
    const int blk = blockIdx.y;
    const int tid = threadIdx.x, lane = tid & 31, w = tid >> 5;
    const int wm = (w & 7) * 32, wn = (w >> 3) * 96;  // warps 0-7 real, 8-15 imag

    for (int e = tid; e < 3072; e += 512) {
        int r = e / 12, q = e % 12;
        cpa16(&Ys[r * 104 + q * 8],
              &g_Y[(size_t)(m0 + r) * CDIM + blk * 96 + q * 8]);
    }
    for (int e = tid; e < 2304; e += 512) {
        int r = e / 12, q = e % 12;
        cpa16(&W1s[r * 104 + q * 8], &g_W1T[(blk * 192 + r) * 96 + q * 8]);
    }
    cp_commit();
    if (tid < 96) {
        int cA = tid * 2;
        float va0, va1, vb0, vb1;
        if (cA < 96) {
            va0 = b1[blk * 96 + cA];       va1 = b1[blk * 96 + cA + 1];
            vb0 = b2[blk * 96 + cA];       vb1 = b2[blk * 96 + cA + 1];
        } else {
            va0 = b1[(NB + blk) * 96 + cA - 96]; va1 = b1[(NB + blk) * 96 + cA - 95];
            vb0 = b2[(NB + blk) * 96 + cA - 96]; vb1 = b2[(NB + blk) * 96 + cA - 95];
        }
        bias1h[tid] = __floats2half2_rn(va0, va1);
        bias2h[tid] = __floats2half2_rn(vb0, vb1);
    }
    cp_wait<0>();
    __syncthreads();

    const int g = lane >> 2, c2 = (lane & 3) << 1;
    const __half2 zero2 = __float2half2_rn(0.f);
    const __half2 lam2 = __float2half2_rn(LAMBDA);

    uint32_t acc[2][12][2];
#pragma unroll
    for (int a = 0; a < 2; a++)
#pragma unroll
        for (int b = 0; b < 12; b++) { acc[a][b][0] = 0u; acc[a][b][1] = 0u; }

    // ---- GEMM-A: [256,96] @ [96,192] ----
#pragma unroll
    for (int k0 = 0; k0 < 96; k0 += 16) {
        uint32_t af[2][4];
#pragma unroll
        for (int mt = 0; mt < 2; mt++)
            ldsm4(af[mt][0], af[mt][1], af[mt][2], af[mt][3],
                  &Ys[(wm + mt * 16 + (lane & 15)) * 104 + k0 + ((lane >> 4) << 3)]);
#pragma unroll
        for (int q = 0; q < 6; q++) {
            uint32_t bfr[2][2];
            int nrow = wn + q * 16 + (lane & 7) + ((lane >> 4) & 1) * 8;
            int koff = k0 + (lane & 8);
            ldsm4(bfr[0][0], bfr[0][1], bfr[1][0], bfr[1][1], &W1s[nrow * 104 + koff]);
#pragma unroll
            for (int mt = 0; mt < 2; mt++) {
                mma_h(acc[mt][2 * q + 0][0], acc[mt][2 * q + 0][1], af[mt], bfr[0]);
                mma_h(acc[mt][2 * q + 1][0], acc[mt][2 * q + 1][1], af[mt], bfr[1]);
            }
        }
    }
    __syncthreads();            // all warps done reading R0 (Ys/W1s)

    for (int e = tid; e < 4608; e += 512) {          // W2 load overlaps epilogue A
        int r = e / 24, q = e % 24;
        cpa16(&W2s[r * 200 + q * 8], &g_W2T[(blk * 192 + r) * 192 + q * 8]);
    }
    cp_commit();

#pragma unroll
    for (int mt = 0; mt < 2; mt++) {
#pragma unroll
        for (int nt = 0; nt < 12; nt++) {
            int col = wn + nt * 8 + c2;
            int r0 = wm + mt * 16 + g;
            __half2 bia = bias1h[col >> 1];
            __half2 v0 = __hmax2(__hadd2(*(__half2*)&acc[mt][nt][0], bia), zero2);
            __half2 v1 = __hmax2(__hadd2(*(__half2*)&acc[mt][nt][1], bia), zero2);
            *(__half2*)&O1s[r0 * 200 + col] = v0;
            *(__half2*)&O1s[(r0 + 8) * 200 + col] = v1;
        }
    }
    cp_wait<0>();
    __syncthreads();

    // ---- GEMM-B: [256,192] @ [192,192] ----
#pragma unroll
    for (int a = 0; a < 2; a++)
#pragma unroll
        for (int b = 0; b < 12; b++) { acc[a][b][0] = 0u; acc[a][b][1] = 0u; }

#pragma unroll
    for (int k0 = 0; k0 < 192; k0 += 16) {
        uint32_t af[2][4];
#pragma unroll
        for (int mt = 0; mt < 2; mt++)
            ldsm4(af[mt][0], af[mt][1], af[mt][2], af[mt][3],
                  &O1s[(wm + mt * 16 + (lane & 15)) * 200 + k0 + ((lane >> 4) << 3)]);
#pragma unroll
        for (int q = 0; q < 6; q++) {
            uint32_t bfr[2][2];
            int nrow = wn + q * 16 + (lane & 7) + ((lane >> 4) & 1) * 8;
            int koff = k0 + (lane & 8);
            ldsm4(bfr[0][0], bfr[0][1], bfr[1][0], bfr[1][1], &W2s[nrow * 200 + koff]);
#pragma unroll
            for (int mt = 0; mt < 2; mt++) {
                mma_h(acc[mt][2 * q + 0][0], acc[mt][2 * q + 0][1], af[mt], bfr[0]);
                mma_h(acc[mt][2 * q + 1][0], acc[mt][2 * q + 1][1], af[mt], bfr[1]);
            }
        }
    }
    __syncthreads();

    // epilogue B: bias + softshrink; imag warps export via exchange buffer
#pragma unroll
    for (int mt = 0; mt < 2; mt++) {
#pragma unroll
        for (int nt = 0; nt < 12; nt++) {
            int col = wn + nt * 8 + c2;
            __half2 bia = bias2h[col >> 1];
#pragma unroll
            for (int j = 0; j < 2; j++) {
                __half2 v = __hadd2(*(__half2*)&acc[mt][nt][j], bia);
                __half2 t = __hmax2(__hsub2(__habs2(v), lam2), zero2);
                uint32_t s = (*(uint32_t*)&t) | ((*(uint32_t*)&v) & 0x80008000u);
                acc[mt][nt][j] = s;
            }
            if (w >= 8) {
                int r0 = wm + mt * 16 + g;
                int colL = col - 96;
                *(uint32_t*)&Ys[r0 * 104 + colL]       = acc[mt][nt][0];
                *(uint32_t*)&Ys[(r0 + 8) * 104 + colL] = acc[mt][nt][1];
            }
        }
    }
    __syncthreads();

    if (w < 8) {
#pragma unroll
        for (int mt = 0; mt < 2; mt++) {
#pragma unroll
            for (int nt = 0; nt < 12; nt++) {
                int col = nt * 8 + c2;
                int r0 = wm + mt * 16 + g;
                __half2 i0 = *(__half2*)&Ys[r0 * 104 + col];
                __half2 i1 = *(__half2*)&Ys[(r0 + 8) * 104 + col];
                __half2 d0 = __hsub2(*(__half2*)&acc[mt][nt][0], i0);
                __half2 d1 = __hsub2(*(__half2*)&acc[mt][nt][1], i1);
                *(__half2*)&g_D[(size_t)(m0 + r0) * CDIM + blk * 96 + col] = d0;
                *(__half2*)&g_D[(size_t)(m0 + r0 + 8) * CDIM + blk * 96 + col] = d1;
            }
        }
    }
}

// ---------------- launch ----------------
extern "C" void kernel_launch(void* const* d_in, const int* in_sizes, int n_in,
                              void* d_out, int out_size) {
    const float* x  = (const float*)d_in[0];
    const float* w1 = (const float*)d_in[1];
    const float* b1 = (const float*)d_in[2];
    const float* w2 = (const float*)d_in[3];
    const float* b2 = (const float*)d_in[4];
    float* out = (float*)d_out;

    cudaFuncSetAttribute(gemm768<0>, cudaFuncAttributeMaxDynamicSharedMemorySize, G_SMEM);
    cudaFuncSetAttribute(gemm768<1>, cudaFuncAttributeMaxDynamicSharedMemorySize, G_SMEM);
    cudaFuncSetAttribute(mlp_kernel, cudaFuncAttributeMaxDynamicSharedMemorySize, MLP_SMEM);

    // launch order: gemm768<1> is the 4th launch -> gets the ncu capture slot
    prep_all<<<PREP_BLOCKS, 256>>>(x, w1, w2);
    gemm768<0><<<dim3(CDIM / 128, ROWS_TOTAL / 256), 256, G_SMEM>>>(nullptr, nullptr);
    mlp_kernel<<<dim3(ROWS_TOTAL / 256, NB), 512, MLP_SMEM>>>(b1, b2);
    gemm768<1><<<dim3(CDIM / 128, ROWS_TOTAL / 256), 256, G_SMEM>>>(x, out);
}

// round 10
// speedup vs baseline: 1.0207x; 1.0207x over previous
#include <cuda_runtime.h>
#include <cuda_fp16.h>
#include <cstdint>

#define DINLINE __device__ __forceinline__

// ---------------- problem constants ----------------
#define ROWS_TOTAL 32768      // B*N = 8*4096
#define CDIM 768
#define NB 8
#define INV_NTOT (1.0f/25165824.0f)   // 1 / (B*H*W*C)
#define LAMBDA 0.01f

// ---------------- device scratch ----------------
__device__ __half g_cas[CDIM * CDIM];                  // symmetric
__device__ __half g_Xh[(size_t)ROWS_TOTAL * CDIM];
__device__ __half g_Y[(size_t)ROWS_TOTAL * CDIM];
__device__ __half g_D[(size_t)ROWS_TOTAL * CDIM];
__device__ __half g_W1T[NB * 192 * 96];
__device__ __half g_W2T[NB * 192 * 192];

// ---------------- asm helpers ----------------
DINLINE void ldsm4(uint32_t& r0, uint32_t& r1, uint32_t& r2, uint32_t& r3, const void* p) {
    uint32_t a = (uint32_t)__cvta_generic_to_shared(p);
    asm volatile("ldmatrix.sync.aligned.m8n8.x4.shared.b16 {%0,%1,%2,%3}, [%4];"
                 : "=r"(r0), "=r"(r1), "=r"(r2), "=r"(r3) : "r"(a));
}
// fp16 accumulate (2x rate): C/D = 2 x f16x2 regs
DINLINE void mma_h(uint32_t& c0, uint32_t& c1, const uint32_t* a, const uint32_t* b) {
    asm volatile("mma.sync.aligned.m16n8k16.row.col.f16.f16.f16.f16 "
                 "{%0,%1}, {%2,%3,%4,%5}, {%6,%7}, {%0,%1};"
                 : "+r"(c0), "+r"(c1)
                 : "r"(a[0]), "r"(a[1]), "r"(a[2]), "r"(a[3]),
                   "r"(b[0]), "r"(b[1]));
}
DINLINE void cpa16(void* smem, const void* g) {
    uint32_t a = (uint32_t)__cvta_generic_to_shared(smem);
    asm volatile("cp.async.cg.shared.global [%0], [%1], 16;" :: "r"(a), "l"(g));
}
DINLINE void cp_commit() { asm volatile("cp.async.commit_group;"); }
template<int N> DINLINE void cp_wait() { asm volatile("cp.async.wait_group %0;" :: "n"(N)); }

// ---------------- prep kernels (two launches) ----------------
constexpr int PX_BLOCKS  = 24576;   // 6,291,456 float4 / 256
constexpr int PCAS_BLOCKS = 2304;   // 589,824 / 256
constexpr int PW1_BLOCKS = 576;     // 147,456 / 256
constexpr int PW2_BLOCKS = 1152;    // 294,912 / 256
constexpr int PREST_BLOCKS = PCAS_BLOCKS + PW1_BLOCKS + PW2_BLOCKS;

__global__ void prep_x_k(const float* __restrict__ x) {
    size_t i = ((size_t)blockIdx.x * 256 + threadIdx.x) * 4;
    float4 v = *(const float4*)&x[i];
    __half2 h0, h1;
    h0.x = __float2half(v.x); h0.y = __float2half(v.y);
    h1.x = __float2half(v.z); h1.y = __float2half(v.w);
    *(__half2*)&g_Xh[i]     = h0;
    *(__half2*)&g_Xh[i + 2] = h1;
}

__global__ void prep_rest(const float* __restrict__ w1,
                          const float* __restrict__ w2) {
    int bid = blockIdx.x, tid = threadIdx.x;
    if (bid < PCAS_BLOCKS) {
        int idx = bid * 256 + tid;
        int i = idx / CDIM, j = idx % CDIM;
        int p = (int)(((long long)i * (long long)j) % CDIM);
        float ang = (float)p * (6.28318530717958647692f / (float)CDIM);
        g_cas[idx] = __float2half(cosf(ang) + sinf(ang));
    } else if (bid < PCAS_BLOCKS + PW1_BLOCKS) {
        int idx = (bid - PCAS_BLOCKS) * 256 + tid;
        int i = idx % 96;
        int n = (idx / 96) % 192;
        int k = idx / (96 * 192);
        float v = (n < 96) ? w1[((0 * NB + k) * 96 + i) * 96 + n]
                           : w1[((1 * NB + k) * 96 + i) * 96 + (n - 96)];
        g_W1T[idx] = __float2half(v);
    } else {
        int idx = (bid - PCAS_BLOCKS - PW1_BLOCKS) * 256 + tid;
        int j = idx % 192;
        int c = (idx / 192) % 192;
        int k = idx / (192 * 192);
        float v;
        if (c < 96) {
            v = (j < 96) ?  w2[((0 * NB + k) * 96 + j) * 96 + c]
                         : -w2[((1 * NB + k) * 96 + (j - 96)) * 96 + c];
        } else {
            int cc = c - 96;
            v = (j < 96) ?  w2[((1 * NB + k) * 96 + j) * 96 + cc]
                         :  w2[((0 * NB + k) * 96 + (j - 96)) * 96 + cc];
        }
        g_W2T[idx] = __float2half(v);
    }
}

// ---------------- big GEMM (R8 config): BM=128, 3-stage, 3 CTAs/SM ----------------
constexpr int G_BK = 32;
constexpr int G_AST = G_BK + 8;
constexpr int G_STAGE_ELEMS = 2 * 128 * G_AST;         // 10240
constexpr int G_SMEM = 3 * G_STAGE_ELEMS * 2;          // 61440 B
constexpr int G_NIT = CDIM / G_BK;                     // 24

DINLINE void g_fill(__half* sh, int s, int k0,
                    const __half* __restrict__ Ag,
                    int m0, int n0, int tid) {
    __half* As = sh + s * G_STAGE_ELEMS;
    __half* Bs = As + 128 * G_AST;
#pragma unroll
    for (int e = tid; e < 512; e += 256) {
        int r = e >> 2, c = (e & 3) << 3;
        cpa16(&As[r * G_AST + c], &Ag[(size_t)(m0 + r) * CDIM + k0 + c]);
        cpa16(&Bs[r * G_AST + c], &g_cas[(size_t)(n0 + r) * CDIM + k0 + c]);
    }
}

template<int MODE>
__global__ void __launch_bounds__(256, 3) gemm768(const float* __restrict__ xbias,
                                                  float* __restrict__ outp) {
    extern __shared__ __half sh[];
    const int n0 = blockIdx.x * 128, m0 = blockIdx.y * 128;
    const int tid = threadIdx.x, lane = tid & 31, w = tid >> 5;
    const int wm = (w & 3) * 32, wn = (w >> 2) * 64;
    const __half* Ag = (MODE == 0) ? g_Xh : g_D;

    uint32_t acc[2][8][2];
#pragma unroll
    for (int a = 0; a < 2; a++)
#pragma unroll
        for (int b = 0; b < 8; b++) { acc[a][b][0] = 0u; acc[a][b][1] = 0u; }

    g_fill(sh, 0, 0, Ag, m0, n0, tid); cp_commit();
    g_fill(sh, 1, G_BK, Ag, m0, n0, tid); cp_commit();

#pragma unroll 1
    for (int it = 0; it < G_NIT; it++) {
        cp_wait<1>();
        __syncthreads();
        if (it + 2 < G_NIT)
            g_fill(sh, (it + 2) % 3, (it + 2) * G_BK, Ag, m0, n0, tid);
        cp_commit();

        const __half* As = sh + (it % 3) * G_STAGE_ELEMS;
        const __half* Bs = As + 128 * G_AST;
#pragma unroll
        for (int kk = 0; kk < G_BK; kk += 16) {
            uint32_t af[2][4];
#pragma unroll
            for (int mt = 0; mt < 2; mt++)
                ldsm4(af[mt][0], af[mt][1], af[mt][2], af[mt][3],
                      &As[(wm + mt * 16 + (lane & 15)) * G_AST + kk + ((lane >> 4) << 3)]);
#pragma unroll
            for (int q = 0; q < 4; q++) {
                uint32_t bfr[2][2];
                int nrow = wn + q * 16 + (lane & 7) + ((lane >> 4) & 1) * 8;
                int koff = kk + (lane & 8);
                ldsm4(bfr[0][0], bfr[0][1], bfr[1][0], bfr[1][1], &Bs[nrow * G_AST + koff]);
#pragma unroll
                for (int mt = 0; mt < 2; mt++) {
                    mma_h(acc[mt][2 * q + 0][0], acc[mt][2 * q + 0][1], af[mt], bfr[0]);
                    mma_h(acc[mt][2 * q + 1][0], acc[mt][2 * q + 1][1], af[mt], bfr[1]);
                }
            }
        }
    }

    const int g = lane >> 2, c2 = (lane & 3) << 1;
#pragma unroll
    for (int mt = 0; mt < 2; mt++) {
#pragma unroll
        for (int nt = 0; nt < 8; nt++) {
            int col = n0 + wn + nt * 8 + c2;
            int row = m0 + wm + mt * 16 + g;
            if (MODE == 0) {
                *(uint32_t*)&g_Y[(size_t)row * CDIM + col]       = acc[mt][nt][0];
                *(uint32_t*)&g_Y[(size_t)(row + 8) * CDIM + col] = acc[mt][nt][1];
            } else {
                float2 v0 = __half22float2(*(__half2*)&acc[mt][nt][0]);
                float2 v1 = __half22float2(*(__half2*)&acc[mt][nt][1]);
                float2 xv0 = *(const float2*)&xbias[(size_t)row * CDIM + col];
                float2 xv1 = *(const float2*)&xbias[(size_t)(row + 8) * CDIM + col];
                float2 o0, o1;
                o0.x = v0.x * INV_NTOT + xv0.x;
                o0.y = v0.y * INV_NTOT + xv0.y;
                o1.x = v1.x * INV_NTOT + xv1.x;
                o1.y = v1.y * INV_NTOT + xv1.y;
                *(float2*)&outp[(size_t)row * CDIM + col] = o0;
                *(float2*)&outp[(size_t)(row + 8) * CDIM + col] = o1;
            }
        }
    }
}

// ---------------- persistent block-diagonal MLP ----------------
// Grid (18, 8): one CTA per SM; CTA owns block `blk` weights (resident) and
// streams 128-row Y tiles with double-buffered cp.async prefetch.
// SMEM: Ys0 26,624 | Ys1 26,624 | W1s 39,936 | W2s 76,800 | O1s 51,200 | bias
constexpr int MLP_SLICES = 18;
constexpr int MLP_TILES = ROWS_TOTAL / 128;            // 256
constexpr int OFF_YS0 = 0;
constexpr int OFF_YS1 = 26624;
constexpr int OFF_W1 = 53248;
constexpr int OFF_W2 = 93184;
constexpr int OFF_O1 = 169984;
constexpr int OFF_BIAS = 221184;
constexpr int MLP_SMEM = 222208;

DINLINE void mlp_fill_y(char* smem, int cb, int t, int blk, int tid) {
    __half* Yd = (__half*)(smem + (cb ? OFF_YS1 : OFF_YS0));
    int m0 = t * 128;
#pragma unroll
    for (int e = tid; e < 1536; e += 256) {
        int r = e / 12, q = e % 12;
        cpa16(&Yd[r * 104 + q * 8],
              &g_Y[(size_t)(m0 + r) * CDIM + blk * 96 + q * 8]);
    }
}

__global__ void __launch_bounds__(256) mlp_kernel(const float* __restrict__ b1,
                                                  const float* __restrict__ b2) {
    extern __shared__ char smem[];
    __half* W1s = (__half*)(smem + OFF_W1);      // 192 x 104
    __half* W2s = (__half*)(smem + OFF_W2);      // 192 x 200
    __half* O1s = (__half*)(smem + OFF_O1);      // 128 x 200
    __half2* bias1h = (__half2*)(smem + OFF_BIAS);
    __half2* bias2h = bias1h + 96;

    const int slice = blockIdx.x;
    const int blk = blockIdx.y;
    const int tid = threadIdx.x, lane = tid & 31, w = tid >> 5;
    const int wm = (w & 3) * 32, wn = (w >> 2) * 96;   // warps 0-3 real, 4-7 imag

    // ---- resident loads: W1, W2, bias, first Y tile ----
#pragma unroll
    for (int e = tid; e < 2304; e += 256) {
        int r = e / 12, q = e % 12;
        cpa16(&W1s[r * 104 + q * 8], &g_W1T[(blk * 192 + r) * 96 + q * 8]);
    }
#pragma unroll
    for (int e = tid; e < 4608; e += 256) {
        int r = e / 24, q = e % 24;
        cpa16(&W2s[r * 200 + q * 8], &g_W2T[(blk * 192 + r) * 192 + q * 8]);
    }
    mlp_fill_y(smem, 0, slice, blk, tid);
    cp_commit();
    if (tid < 96) {
        int cA = tid * 2;
        float va0, va1, vb0, vb1;
        if (cA < 96) {
            va0 = b1[blk * 96 + cA];       va1 = b1[blk * 96 + cA + 1];
            vb0 = b2[blk * 96 + cA];       vb1 = b2[blk * 96 + cA + 1];
        } else {
            va0 = b1[(NB + blk) * 96 + cA - 96]; va1 = b1[(NB + blk) * 96 + cA - 95];
            vb0 = b2[(NB + blk) * 96 + cA - 96]; vb1 = b2[(NB + blk) * 96 + cA - 95];
        }
        bias1h[tid] = __floats2half2_rn(va0, va1);
        bias2h[tid] = __floats2half2_rn(vb0, vb1);
    }
    cp_wait<0>();
    __syncthreads();

    const int g = lane >> 2, c2 = (lane & 3) << 1;
    const __half2 zero2 = __float2half2_rn(0.f);
    const __half2 lam2 = __float2half2_rn(LAMBDA);

    int cb = 0;
#pragma unroll 1
    for (int t = slice; t < MLP_TILES; t += MLP_SLICES) {
        __half* Ys = (__half*)(smem + (cb ? OFF_YS1 : OFF_YS0));
        const int m0 = t * 128;

        // prefetch next Y tile into the other buffer
        if (t + MLP_SLICES < MLP_TILES)
            mlp_fill_y(smem, cb ^ 1, t + MLP_SLICES, blk, tid);
        cp_commit();

        uint32_t acc[2][12][2];
#pragma unroll
        for (int a = 0; a < 2; a++)
#pragma unroll
            for (int b = 0; b < 12; b++) { acc[a][b][0] = 0u; acc[a][b][1] = 0u; }

        // ---- GEMM-A: [128,96] @ [96,192] ----
#pragma unroll
        for (int k0 = 0; k0 < 96; k0 += 16) {
            uint32_t af[2][4];
#pragma unroll
            for (int mt = 0; mt < 2; mt++)
                ldsm4(af[mt][0], af[mt][1], af[mt][2], af[mt][3],
                      &Ys[(wm + mt * 16 + (lane & 15)) * 104 + k0 + ((lane >> 4) << 3)]);
#pragma unroll
            for (int q = 0; q < 6; q++) {
                uint32_t bfr[2][2];
                int nrow = wn + q * 16 + (lane & 7) + ((lane >> 4) & 1) * 8;
                int koff = k0 + (lane & 8);
                ldsm4(bfr[0][0], bfr[0][1], bfr[1][0], bfr[1][1], &W1s[nrow * 104 + koff]);
#pragma unroll
                for (int mt = 0; mt < 2; mt++) {
                    mma_h(acc[mt][2 * q + 0][0], acc[mt][2 * q + 0][1], af[mt], bfr[0]);
                    mma_h(acc[mt][2 * q + 1][0], acc[mt][2 * q + 1][1], af[mt], bfr[1]);
                }
            }
        }

        // epilogue A: bias + relu -> O1s (O1s idle: prev GEMM-B finished last iter)
#pragma unroll
        for (int mt = 0; mt < 2; mt++) {
#pragma unroll
            for (int nt = 0; nt < 12; nt++) {
                int col = wn + nt * 8 + c2;
                int r0 = wm + mt * 16 + g;
                __half2 bia = bias1h[col >> 1];
                __half2 v0 = __hmax2(__hadd2(*(__half2*)&acc[mt][nt][0], bia), zero2);
                __half2 v1 = __hmax2(__hadd2(*(__half2*)&acc[mt][nt][1], bia), zero2);
                *(__half2*)&O1s[r0 * 200 + col] = v0;
                *(__half2*)&O1s[(r0 + 8) * 200 + col] = v1;
            }
        }
        __syncthreads();     // O1s ready; all warps past GEMM-A (Ys reads done)

        // ---- GEMM-B: [128,192] @ [192,192] ----
#pragma unroll
        for (int a = 0; a < 2; a++)
#pragma unroll
            for (int b = 0; b < 12; b++) { acc[a][b][0] = 0u; acc[a][b][1] = 0u; }

#pragma unroll
        for (int k0 = 0; k0 < 192; k0 += 16) {
            uint32_t af[2][4];
#pragma unroll
            for (int mt = 0; mt < 2; mt++)
                ldsm4(af[mt][0], af[mt][1], af[mt][2], af[mt][3],
                      &O1s[(wm + mt * 16 + (lane & 15)) * 200 + k0 + ((lane >> 4) << 3)]);
#pragma unroll
            for (int q = 0; q < 6; q++) {
                uint32_t bfr[2][2];
                int nrow = wn + q * 16 + (lane & 7) + ((lane >> 4) & 1) * 8;
                int koff = k0 + (lane & 8);
                ldsm4(bfr[0][0], bfr[0][1], bfr[1][0], bfr[1][1], &W2s[nrow * 200 + koff]);
#pragma unroll
                for (int mt = 0; mt < 2; mt++) {
                    mma_h(acc[mt][2 * q + 0][0], acc[mt][2 * q + 0][1], af[mt], bfr[0]);
                    mma_h(acc[mt][2 * q + 1][0], acc[mt][2 * q + 1][1], af[mt], bfr[1]);
                }
            }
        }
        __syncthreads();     // all done reading O1s; Ys[cb] free for exchange

        // epilogue B: bias + softshrink; imag warps export via Ys[cb]
#pragma unroll
        for (int mt = 0; mt < 2; mt++) {
#pragma unroll
            for (int nt = 0; nt < 12; nt++) {
                int col = wn + nt * 8 + c2;
                __half2 bia = bias2h[col >> 1];
#pragma unroll
                for (int j = 0; j < 2; j++) {
                    __half2 v = __hadd2(*(__half2*)&acc[mt][nt][j], bia);
                    __half2 tt = __hmax2(__hsub2(__habs2(v), lam2), zero2);
                    uint32_t s = (*(uint32_t*)&tt) | ((*(uint32_t*)&v) & 0x80008000u);
                    acc[mt][nt][j] = s;
                }
                if (w >= 4) {
                    int r0 = wm + mt * 16 + g;
                    int colL = col - 96;
                    *(uint32_t*)&Ys[r0 * 104 + colL]       = acc[mt][nt][0];
                    *(uint32_t*)&Ys[(r0 + 8) * 104 + colL] = acc[mt][nt][1];
                }
            }
        }
        __syncthreads();

        // real warps: d = ss(real) - ss(imag), store g_D
        if (w < 4) {
#pragma unroll
            for (int mt = 0; mt < 2; mt++) {
#pragma unroll
                for (int nt = 0; nt < 12; nt++) {
                    int col = nt * 8 + c2;
                    int r0 = wm + mt * 16 + g;
                    __half2 i0 = *(__half2*)&Ys[r0 * 104 + col];
                    __half2 i1 = *(__half2*)&Ys[(r0 + 8) * 104 + col];
                    __half2 d0 = __hsub2(*(__half2*)&acc[mt][nt][0], i0);
                    __half2 d1 = __hsub2(*(__half2*)&acc[mt][nt][1], i1);
                    *(__half2*)&g_D[(size_t)(m0 + r0) * CDIM + blk * 96 + col] = d0;
                    *(__half2*)&g_D[(size_t)(m0 + r0 + 8) * CDIM + blk * 96 + col] = d1;
                }
            }
        }

        cp_wait<0>();        // next Y tile landed
        __syncthreads();     // exchange reads done; safe to reuse buffers
        cb ^= 1;
    }
}

// ---------------- launch ----------------
extern "C" void kernel_launch(void* const* d_in, const int* in_sizes, int n_in,
                              void* d_out, int out_size) {
    const float* x  = (const float*)d_in[0];
    const float* w1 = (const float*)d_in[1];
    const float* b1 = (const float*)d_in[2];
    const float* w2 = (const float*)d_in[3];
    const float* b2 = (const float*)d_in[4];
    float* out = (float*)d_out;

    cudaFuncSetAttribute(gemm768<0>, cudaFuncAttributeMaxDynamicSharedMemorySize, G_SMEM);
    cudaFuncSetAttribute(gemm768<1>, cudaFuncAttributeMaxDynamicSharedMemorySize, G_SMEM);
    cudaFuncSetAttribute(mlp_kernel, cudaFuncAttributeMaxDynamicSharedMemorySize, MLP_SMEM);

    // launch order: mlp_kernel is the 4th launch -> gets the ncu capture slot
    prep_x_k<<<PX_BLOCKS, 256>>>(x);
    prep_rest<<<PREST_BLOCKS, 256>>>(w1, w2);
    gemm768<0><<<dim3(CDIM / 128, ROWS_TOTAL / 128), 256, G_SMEM>>>(nullptr, nullptr);
    mlp_kernel<<<dim3(MLP_SLICES, NB), 256, MLP_SMEM>>>(b1, b2);
    gemm768<1><<<dim3(CDIM / 128, ROWS_TOTAL / 128), 256, G_SMEM>>>(x, out);
}

// round 11
// speedup vs baseline: 1.0882x; 1.0661x over previous
#include <cuda_runtime.h>
#include <cuda_fp16.h>
#include <cstdint>

#define DINLINE __device__ __forceinline__

// ---------------- problem constants ----------------
#define ROWS_TOTAL 32768      // B*N = 8*4096
#define CDIM 768
#define NB 8
#define INV_NTOT (1.0f/25165824.0f)   // 1 / (B*H*W*C)
#define LAMBDA 0.01f

// ---------------- device scratch ----------------
__device__ __half g_cas[CDIM * CDIM];                  // symmetric
__device__ __half g_Xh[(size_t)ROWS_TOTAL * CDIM];
__device__ __half g_Y[(size_t)ROWS_TOTAL * CDIM];
__device__ __half g_D[(size_t)ROWS_TOTAL * CDIM];
__device__ __half g_W1T[NB * 192 * 96];
__device__ __half g_W2T[NB * 192 * 192];

// ---------------- asm helpers ----------------
DINLINE void ldsm4(uint32_t& r0, uint32_t& r1, uint32_t& r2, uint32_t& r3, const void* p) {
    uint32_t a = (uint32_t)__cvta_generic_to_shared(p);
    asm volatile("ldmatrix.sync.aligned.m8n8.x4.shared.b16 {%0,%1,%2,%3}, [%4];"
                 : "=r"(r0), "=r"(r1), "=r"(r2), "=r"(r3) : "r"(a));
}
// fp16 accumulate (2x rate): C/D = 2 x f16x2 regs
DINLINE void mma_h(uint32_t& c0, uint32_t& c1, const uint32_t* a, const uint32_t* b) {
    asm volatile("mma.sync.aligned.m16n8k16.row.col.f16.f16.f16.f16 "
                 "{%0,%1}, {%2,%3,%4,%5}, {%6,%7}, {%0,%1};"
                 : "+r"(c0), "+r"(c1)
                 : "r"(a[0]), "r"(a[1]), "r"(a[2]), "r"(a[3]),
                   "r"(b[0]), "r"(b[1]));
}
DINLINE void cpa16(void* smem, const void* g) {
    uint32_t a = (uint32_t)__cvta_generic_to_shared(smem);
    asm volatile("cp.async.cg.shared.global [%0], [%1], 16;" :: "r"(a), "l"(g));
}
DINLINE void cp_commit() { asm volatile("cp.async.commit_group;"); }
template<int N> DINLINE void cp_wait() { asm volatile("cp.async.wait_group %0;" :: "n"(N)); }

// ---------------- prep kernels (three launches; gemm0 -> ncu slot 4) ----------------
constexpr int PX_BLOCKS  = 24576;   // 6,291,456 float4 / 256
constexpr int PCAS_BLOCKS = 2304;   // 589,824 / 256
constexpr int PW1_BLOCKS = 576;     // 147,456 / 256
constexpr int PW2_BLOCKS = 1152;    // 294,912 / 256

__global__ void prep_x_k(const float* __restrict__ x) {
    size_t i = ((size_t)blockIdx.x * 256 + threadIdx.x) * 4;
    float4 v = *(const float4*)&x[i];
    __half2 h0, h1;
    h0.x = __float2half(v.x); h0.y = __float2half(v.y);
    h1.x = __float2half(v.z); h1.y = __float2half(v.w);
    *(__half2*)&g_Xh[i]     = h0;
    *(__half2*)&g_Xh[i + 2] = h1;
}

__global__ void prep_cas_k() {
    int idx = blockIdx.x * 256 + threadIdx.x;
    int i = idx / CDIM, j = idx % CDIM;
    int p = (int)(((long long)i * (long long)j) % CDIM);
    float ang = (float)p * (6.28318530717958647692f / (float)CDIM);
    g_cas[idx] = __float2half(cosf(ang) + sinf(ang));
}

__global__ void prep_w_k(const float* __restrict__ w1,
                         const float* __restrict__ w2) {
    int bid = blockIdx.x, tid = threadIdx.x;
    if (bid < PW1_BLOCKS) {
        int idx = bid * 256 + tid;
        int i = idx % 96;
        int n = (idx / 96) % 192;
        int k = idx / (96 * 192);
        float v = (n < 96) ? w1[((0 * NB + k) * 96 + i) * 96 + n]
                           : w1[((1 * NB + k) * 96 + i) * 96 + (n - 96)];
        g_W1T[idx] = __float2half(v);
    } else {
        int idx = (bid - PW1_BLOCKS) * 256 + tid;
        int j = idx % 192;
        int c = (idx / 192) % 192;
        int k = idx / (192 * 192);
        float v;
        if (c < 96) {
            v = (j < 96) ?  w2[((0 * NB + k) * 96 + j) * 96 + c]
                         : -w2[((1 * NB + k) * 96 + (j - 96)) * 96 + c];
        } else {
            int cc = c - 96;
            v = (j < 96) ?  w2[((1 * NB + k) * 96 + j) * 96 + cc]
                         :  w2[((0 * NB + k) * 96 + (j - 96)) * 96 + cc];
        }
        g_W2T[idx] = __float2half(v);
    }
}

// ---------------- big GEMM: XOR-swizzled SMEM, 48KB, 4 CTAs/SM ----------------
// Tile row = 32 halves (64B) = 4 x 16B chunks. phys_chunk = chunk ^ ((row>>1)&3).
constexpr int G_BK = 32;
constexpr int G_STAGE_ELEMS = 2 * 128 * 32;            // 8192 halves = 16KB
constexpr int G_SMEM = 3 * G_STAGE_ELEMS * 2;          // 49152 B -> 4 CTAs/SM
constexpr int G_NIT = CDIM / G_BK;                     // 24

DINLINE uint32_t g_off(int r, int chunk) {             // offset in halves
    return (uint32_t)(r * 32 + ((chunk ^ ((r >> 1) & 3)) << 3));
}

DINLINE void g_fill(__half* sh, int s, int k0,
                    const __half* __restrict__ Ag,
                    int m0, int n0, int tid) {
    __half* As = sh + s * G_STAGE_ELEMS;
    __half* Bs = As + 128 * 32;
#pragma unroll
    for (int e = tid; e < 512; e += 256) {
        int r = e >> 2, c = e & 3;
        uint32_t off = g_off(r, c);
        cpa16(&As[off], &Ag[(size_t)(m0 + r) * CDIM + k0 + c * 8]);
        cpa16(&Bs[off], &g_cas[(size_t)(n0 + r) * CDIM + k0 + c * 8]);
    }
}

template<int MODE>
__global__ void __launch_bounds__(256, 4) gemm768(const float* __restrict__ xbias,
                                                  float* __restrict__ outp) {
    extern __shared__ __half sh[];
    const int n0 = blockIdx.x * 128, m0 = blockIdx.y * 128;
    const int tid = threadIdx.x, lane = tid & 31, w = tid >> 5;
    const int wm = (w & 3) * 32, wn = (w >> 2) * 64;
    const __half* Ag = (MODE == 0) ? g_Xh : g_D;

    uint32_t acc[2][8][2];
#pragma unroll
    for (int a = 0; a < 2; a++)
#pragma unroll
        for (int b = 0; b < 8; b++) { acc[a][b][0] = 0u; acc[a][b][1] = 0u; }

    g_fill(sh, 0, 0, Ag, m0, n0, tid); cp_commit();
    g_fill(sh, 1, G_BK, Ag, m0, n0, tid); cp_commit();

#pragma unroll 1
    for (int it = 0; it < G_NIT; it++) {
        cp_wait<1>();
        __syncthreads();
        if (it + 2 < G_NIT)
            g_fill(sh, (it + 2) % 3, (it + 2) * G_BK, Ag, m0, n0, tid);
        cp_commit();

        const __half* As = sh + (it % 3) * G_STAGE_ELEMS;
        const __half* Bs = As + 128 * 32;
#pragma unroll
        for (int kk = 0; kk < G_BK; kk += 16) {
            uint32_t af[2][4];
#pragma unroll
            for (int mt = 0; mt < 2; mt++) {
                int row = wm + mt * 16 + (lane & 15);
                int koff = kk + ((lane >> 4) << 3);
                ldsm4(af[mt][0], af[mt][1], af[mt][2], af[mt][3],
                      &As[g_off(row, koff >> 3)]);
            }
#pragma unroll
            for (int q = 0; q < 4; q++) {
                uint32_t bfr[2][2];
                int nrow = wn + q * 16 + (lane & 7) + ((lane >> 4) & 1) * 8;
                int koff = kk + (lane & 8);
                ldsm4(bfr[0][0], bfr[0][1], bfr[1][0], bfr[1][1],
                      &Bs[g_off(nrow, koff >> 3)]);
#pragma unroll
                for (int mt = 0; mt < 2; mt++) {
                    mma_h(acc[mt][2 * q + 0][0], acc[mt][2 * q + 0][1], af[mt], bfr[0]);
                    mma_h(acc[mt][2 * q + 1][0], acc[mt][2 * q + 1][1], af[mt], bfr[1]);
                }
            }
        }
    }

    const int g = lane >> 2, c2 = (lane & 3) << 1;
#pragma unroll
    for (int mt = 0; mt < 2; mt++) {
#pragma unroll
        for (int nt = 0; nt < 8; nt++) {
            int col = n0 + wn + nt * 8 + c2;
            int row = m0 + wm + mt * 16 + g;
            if (MODE == 0) {
                *(uint32_t*)&g_Y[(size_t)row * CDIM + col]       = acc[mt][nt][0];
                *(uint32_t*)&g_Y[(size_t)(row + 8) * CDIM + col] = acc[mt][nt][1];
            } else {
                float2 v0 = __half22float2(*(__half2*)&acc[mt][nt][0]);
                float2 v1 = __half22float2(*(__half2*)&acc[mt][nt][1]);
                float2 xv0 = *(const float2*)&xbias[(size_t)row * CDIM + col];
                float2 xv1 = *(const float2*)&xbias[(size_t)(row + 8) * CDIM + col];
                float2 o0, o1;
                o0.x = v0.x * INV_NTOT + xv0.x;
                o0.y = v0.y * INV_NTOT + xv0.y;
                o1.x = v1.x * INV_NTOT + xv1.x;
                o1.y = v1.y * INV_NTOT + xv1.y;
                *(float2*)&outp[(size_t)row * CDIM + col] = o0;
                *(float2*)&outp[(size_t)(row + 8) * CDIM + col] = o1;
            }
        }
    }
}

// ---------------- fused block-diagonal MLP: 512 threads, 256-row tiles (R8) ----------------
constexpr int MLP_SMEM = 196352;

__global__ void __launch_bounds__(512) mlp_kernel(const float* __restrict__ b1,
                                                  const float* __restrict__ b2) {
    extern __shared__ char smem[];
    __half* Ys  = (__half*)(smem);               // 256 x 104 (phase A / exchange)
    __half* W1s = (__half*)(smem + 53248);       // 192 x 104
    __half* W2s = (__half*)(smem);               // 192 x 200 (phase B, overlaps R0)
    __half* O1s = (__half*)(smem + 93184);       // 256 x 200
    __half2* bias1h = (__half2*)(smem + 195584); // 96 pairs
    __half2* bias2h = bias1h + 96;

    const int m0 = blockIdx.x * 256;
    const int blk = blockIdx.y;
    const int tid = threadIdx.x, lane = tid & 31, w = tid >> 5;
    const int wm = (w & 7) * 32, wn = (w >> 3) * 96;  // warps 0-7 real, 8-15 imag

    for (int e = tid; e < 3072; e += 512) {
        int r = e / 12, q = e % 12;
        cpa16(&Ys[r * 104 + q * 8],
              &g_Y[(size_t)(m0 + r) * CDIM + blk * 96 + q * 8]);
    }
    for (int e = tid; e < 2304; e += 512) {
        int r = e / 12, q = e % 12;
        cpa16(&W1s[r * 104 + q * 8], &g_W1T[(blk * 192 + r) * 96 + q * 8]);
    }
    cp_commit();
    if (tid < 96) {
        int cA = tid * 2;
        float va0, va1, vb0, vb1;
        if (cA < 96) {
            va0 = b1[blk * 96 + cA];       va1 = b1[blk * 96 + cA + 1];
            vb0 = b2[blk * 96 + cA];       vb1 = b2[blk * 96 + cA + 1];
        } else {
            va0 = b1[(NB + blk) * 96 + cA - 96]; va1 = b1[(NB + blk) * 96 + cA - 95];
            vb0 = b2[(NB + blk) * 96 + cA - 96]; vb1 = b2[(NB + blk) * 96 + cA - 95];
        }
        bias1h[tid] = __floats2half2_rn(va0, va1);
        bias2h[tid] = __floats2half2_rn(vb0, vb1);
    }
    cp_wait<0>();
    __syncthreads();

    const int g = lane >> 2, c2 = (lane & 3) << 1;
    const __half2 zero2 = __float2half2_rn(0.f);
    const __half2 lam2 = __float2half2_rn(LAMBDA);

    uint32_t acc[2][12][2];
#pragma unroll
    for (int a = 0; a < 2; a++)
#pragma unroll
        for (int b = 0; b < 12; b++) { acc[a][b][0] = 0u; acc[a][b][1] = 0u; }

    // ---- GEMM-A: [256,96] @ [96,192] ----
#pragma unroll
    for (int k0 = 0; k0 < 96; k0 += 16) {
        uint32_t af[2][4];
#pragma unroll
        for (int mt = 0; mt < 2; mt++)
            ldsm4(af[mt][0], af[mt][1], af[mt][2], af[mt][3],
                  &Ys[(wm + mt * 16 + (lane & 15)) * 104 + k0 + ((lane >> 4) << 3)]);
#pragma unroll
        for (int q = 0; q < 6; q++) {
            uint32_t bfr[2][2];
            int nrow = wn + q * 16 + (lane & 7) + ((lane >> 4) & 1) * 8;
            int koff = k0 + (lane & 8);
            ldsm4(bfr[0][0], bfr[0][1], bfr[1][0], bfr[1][1], &W1s[nrow * 104 + koff]);
#pragma unroll
            for (int mt = 0; mt < 2; mt++) {
                mma_h(acc[mt][2 * q + 0][0], acc[mt][2 * q + 0][1], af[mt], bfr[0]);
                mma_h(acc[mt][2 * q + 1][0], acc[mt][2 * q + 1][1], af[mt], bfr[1]);
            }
        }
    }
    __syncthreads();            // all warps done reading R0 (Ys/W1s)

    for (int e = tid; e < 4608; e += 512) {          // W2 load overlaps epilogue A
        int r = e / 24, q = e % 24;
        cpa16(&W2s[r * 200 + q * 8], &g_W2T[(blk * 192 + r) * 192 + q * 8]);
    }
    cp_commit();

#pragma unroll
    for (int mt = 0; mt < 2; mt++) {
#pragma unroll
        for (int nt = 0; nt < 12; nt++) {
            int col = wn + nt * 8 + c2;
            int r0 = wm + mt * 16 + g;
            __half2 bia = bias1h[col >> 1];
            __half2 v0 = __hmax2(__hadd2(*(__half2*)&acc[mt][nt][0], bia), zero2);
            __half2 v1 = __hmax2(__hadd2(*(__half2*)&acc[mt][nt][1], bia), zero2);
            *(__half2*)&O1s[r0 * 200 + col] = v0;
            *(__half2*)&O1s[(r0 + 8) * 200 + col] = v1;
        }
    }
    cp_wait<0>();
    __syncthreads();

    // ---- GEMM-B: [256,192] @ [192,192] ----
#pragma unroll
    for (int a = 0; a < 2; a++)
#pragma unroll
        for (int b = 0; b < 12; b++) { acc[a][b][0] = 0u; acc[a][b][1] = 0u; }

#pragma unroll
    for (int k0 = 0; k0 < 192; k0 += 16) {
        uint32_t af[2][4];
#pragma unroll
        for (int mt = 0; mt < 2; mt++)
            ldsm4(af[mt][0], af[mt][1], af[mt][2], af[mt][3],
                  &O1s[(wm + mt * 16 + (lane & 15)) * 200 + k0 + ((lane >> 4) << 3)]);
#pragma unroll
        for (int q = 0; q < 6; q++) {
            uint32_t bfr[2][2];
            int nrow = wn + q * 16 + (lane & 7) + ((lane >> 4) & 1) * 8;
            int koff = k0 + (lane & 8);
            ldsm4(bfr[0][0], bfr[0][1], bfr[1][0], bfr[1][1], &W2s[nrow * 200 + koff]);
#pragma unroll
            for (int mt = 0; mt < 2; mt++) {
                mma_h(acc[mt][2 * q + 0][0], acc[mt][2 * q + 0][1], af[mt], bfr[0]);
                mma_h(acc[mt][2 * q + 1][0], acc[mt][2 * q + 1][1], af[mt], bfr[1]);
            }
        }
    }
    __syncthreads();

    // epilogue B: bias + softshrink; imag warps export via exchange buffer
#pragma unroll
    for (int mt = 0; mt < 2; mt++) {
#pragma unroll
        for (int nt = 0; nt < 12; nt++) {
            int col = wn + nt * 8 + c2;
            __half2 bia = bias2h[col >> 1];
#pragma unroll
            for (int j = 0; j < 2; j++) {
                __half2 v = __hadd2(*(__half2*)&acc[mt][nt][j], bia);
                __half2 t = __hmax2(__hsub2(__habs2(v), lam2), zero2);
                uint32_t s = (*(uint32_t*)&t) | ((*(uint32_t*)&v) & 0x80008000u);
                acc[mt][nt][j] = s;
            }
            if (w >= 8) {
                int r0 = wm + mt * 16 + g;
                int colL = col - 96;
                *(uint32_t*)&Ys[r0 * 104 + colL]       = acc[mt][nt][0];
                *(uint32_t*)&Ys[(r0 + 8) * 104 + colL] = acc[mt][nt][1];
            }
        }
    }
    __syncthreads();

    if (w < 8) {
#pragma unroll
        for (int mt = 0; mt < 2; mt++) {
#pragma unroll
            for (int nt = 0; nt < 12; nt++) {
                int col = nt * 8 + c2;
                int r0 = wm + mt * 16 + g;
                __half2 i0 = *(__half2*)&Ys[r0 * 104 + col];
                __half2 i1 = *(__half2*)&Ys[(r0 + 8) * 104 + col];
                __half2 d0 = __hsub2(*(__half2*)&acc[mt][nt][0], i0);
                __half2 d1 = __hsub2(*(__half2*)&acc[mt][nt][1], i1);
                *(__half2*)&g_D[(size_t)(m0 + r0) * CDIM + blk * 96 + col] = d0;
                *(__half2*)&g_D[(size_t)(m0 + r0 + 8) * CDIM + blk * 96 + col] = d1;
            }
        }
    }
}

// ---------------- launch ----------------
extern "C" void kernel_launch(void* const* d_in, const int* in_sizes, int n_in,
                              void* d_out, int out_size) {
    const float* x  = (const float*)d_in[0];
    const float* w1 = (const float*)d_in[1];
    const float* b1 = (const float*)d_in[2];
    const float* w2 = (const float*)d_in[3];
    const float* b2 = (const float*)d_in[4];
    float* out = (float*)d_out;

    cudaFuncSetAttribute(gemm768<0>, cudaFuncAttributeMaxDynamicSharedMemorySize, G_SMEM);
    cudaFuncSetAttribute(gemm768<1>, cudaFuncAttributeMaxDynamicSharedMemorySize, G_SMEM);
    cudaFuncSetAttribute(mlp_kernel, cudaFuncAttributeMaxDynamicSharedMemorySize, MLP_SMEM);

    // launch order: gemm768<0> is the 4th launch -> gets the ncu capture slot
    prep_x_k<<<PX_BLOCKS, 256>>>(x);
    prep_cas_k<<<PCAS_BLOCKS, 256>>>();
    prep_w_k<<<PW1_BLOCKS + PW2_BLOCKS, 256>>>(w1, w2);
    gemm768<0><<<dim3(CDIM / 128, ROWS_TOTAL / 128), 256, G_SMEM>>>(nullptr, nullptr);
    mlp_kernel<<<dim3(ROWS_TOTAL / 256, NB), 512, MLP_SMEM>>>(b1, b2);
    gemm768<1><<<dim3(CDIM / 128, ROWS_TOTAL / 128), 256, G_SMEM>>>(x, out);
}